// round 15
// baseline (speedup 1.0000x reference)
#include <cuda_runtime.h>

typedef unsigned long long ull;

#define DEV __device__ __forceinline__

DEV ull pk2(float x) { ull r; asm("mov.b64 %0, {%1, %1};" : "=l"(r) : "f"(x)); return r; }
DEV void upk(ull v, float& a, float& b) { asm("mov.b64 {%0, %1}, %2;" : "=f"(a), "=f"(b) : "l"(v)); }
DEV void fma2(ull& d, ull a, ull b) { asm("fma.rn.f32x2 %0, %1, %2, %0;" : "+l"(d) : "l"(a), "l"(b)); }

// fast exp on the FMA pipe (no MUFU). exp(a) for a <= 0; exact 0 below -87.
DEV float fexp(float a) {
    const float L2E = 1.4426950408889634f;
    float z = fmaf(a, L2E, 12582912.0f);
    int   i = __float_as_int(z);
    float nf = z - 12582912.0f;
    float f = fmaf(a, L2E, -nf);
    float p =           1.3333558146e-3f;
    p = fmaf(p, f,      9.6181291076e-3f);
    p = fmaf(p, f,      5.5504108664e-2f);
    p = fmaf(p, f,      2.4022650696e-1f);
    p = fmaf(p, f,      6.9314718056e-1f);
    p = fmaf(p, f,      1.0f);
    float s = __int_as_float((i - 1262485377) << 23);
    float r = s * p;
    return a > -87.0f ? r : 0.0f;
}

// ---------------- problem constants ----------------
constexpr int HW   = 1600;
constexpr int NPOS = 51200;
constexpr int C0   = 64;
constexpr int K0   = 2048;
constexpr int C1   = 256;
constexpr int K1N  = 512;
constexpr int CAP  = 32;       // max stored actives per row

constexpr size_t OFF_X3  = 0;
constexpr size_t OFF_QX0 = 13107200;
constexpr size_t OFF_QX3 = 16384000;
constexpr size_t OFF_A0  = 29491200;
constexpr size_t OFF_A3  = 134348800;
constexpr size_t OFF_D0  = 160563200;
constexpr size_t OFF_D3  = 265420800;

// ---------------- scratch ----------------
__device__ __align__(16) float g_xn0[NPOS];
__device__ __align__(16) float g_xn3[NPOS];
__device__ __align__(16) float g_en0[K0];
__device__ __align__(16) float g_en1[K1N];
__device__ __align__(16) float g_dm0[NPOS];
__device__ __align__(16) float g_iz0[NPOS];
__device__ __align__(16) float g_dm3[NPOS];
__device__ __align__(16) float g_iz3[NPOS];
__device__ float g_gate;
__device__ __align__(16) float g_y1[(size_t)NPOS * C1];     // head hidden, later reused as qraw3
__device__ __align__(16) float g_qraw0[(size_t)NPOS * C0];
__device__ __align__(16) int   g_actk0[(size_t)NPOS * CAP];
__device__ __align__(16) float g_actw0[(size_t)NPOS * CAP];
__device__ __align__(16) int   g_cnt0[NPOS];
__device__ __align__(16) int   g_actk1[(size_t)NPOS * CAP];
__device__ __align__(16) float g_actw1[(size_t)NPOS * CAP];
__device__ __align__(16) int   g_cnt1[NPOS];

// ---------------- prep: codebook row norms + gate ----------------
__global__ void prep_kernel(const float* __restrict__ vq0, const float* __restrict__ vq1,
                            const int* __restrict__ cur) {
    int bid = blockIdx.x, t = threadIdx.x;
    if (bid == 0 && t == 0) {
        int ci = *cur;
        float gg = (10000 - ci) / 10000.f;
        g_gate = gg > 0.f ? gg : 0.f;
    }
    float s = 0.f;
    if (bid < K0) {
        float v = vq0[bid * 64 + t];
        s = v * v;
    } else {
        int r = bid - K0;
        #pragma unroll
        for (int i = 0; i < 4; i++) { float v = vq1[r * 256 + i * 64 + t]; s += v * v; }
    }
    #pragma unroll
    for (int o = 16; o; o >>= 1) s += __shfl_xor_sync(0xffffffffu, s, o);
    __shared__ float sm[2];
    if ((t & 31) == 0) sm[t >> 5] = s;
    __syncthreads();
    if (t == 0) {
        float r = sm[0] + sm[1];
        if (bid < K0) g_en0[bid] = r; else g_en1[bid - K0] = r;
    }
}

// ---------------- per-position squared norms (X in BCHW) ----------------
template<int C>
__global__ void xnorm_kernel(const float* __restrict__ X, float* __restrict__ out) {
    int n = blockIdx.x * 256 + threadIdx.x;
    int b = n / HW, hw = n % HW;
    const float* p = X + (size_t)b * C * HW + hw;
    float s = 0.f;
    #pragma unroll 8
    for (int c = 0; c < C; c++) { float v = p[(size_t)c * HW]; s += v * v; }
    out[n] = s;
}

// ---------------- generic FFMA2 GEMM (R8 proven body) ----------------
template<int CDIM, int XB, int OB, int EPI, int KTOT>
__global__ __launch_bounds__(256) void gemm_kernel(
    const float* __restrict__ X, const float* __restrict__ E,
    const float* __restrict__ XN, const float* __restrict__ EB,
    float* __restrict__ OUT) {
    constexpr int XS = 68, ES = 260;
    __shared__ __align__(16) float xs[16 * XS];
    __shared__ __align__(16) float es[16 * ES];
    int t = threadIdx.x;
    int p0 = (t & 15) * 4, k0 = (t >> 4) * 16;
    int pt = blockIdx.y;
    int kg0 = blockIdx.x * 256;
    int b = pt / 25, hw0 = (pt % 25) * 64;
    int n0 = pt * 64;
    size_t xbase = XB ? ((size_t)b * CDIM * HW + hw0) : ((size_t)n0 * CDIM);

    ull acc[4][8];
    #pragma unroll
    for (int p = 0; p < 4; p++)
        #pragma unroll
        for (int j = 0; j < 8; j++) acc[p][j] = 0ull;

    #pragma unroll 1
    for (int cc = 0; cc < CDIM; cc += 16) {
        __syncthreads();
        #pragma unroll
        for (int i = 0; i < 4; i++) {
            int id = t + i * 256;
            if (XB) {
                int c = id >> 6, p = id & 63;
                xs[c * XS + p] = X[xbase + (size_t)(cc + c) * HW + p];
            } else {
                int p = id >> 4, c = id & 15;
                xs[c * XS + p] = X[xbase + (size_t)p * CDIM + cc + c];
            }
        }
        #pragma unroll
        for (int i = 0; i < 16; i++) {
            int id = t + i * 256;
            int k = id >> 4, c = id & 15;
            es[c * ES + k] = E[(size_t)(kg0 + k) * CDIM + cc + c];
        }
        __syncthreads();
        #pragma unroll
        for (int c = 0; c < 16; c++) {
            float4 xv = *(const float4*)&xs[c * XS + p0];
            ull xd0 = pk2(xv.x), xd1 = pk2(xv.y), xd2 = pk2(xv.z), xd3 = pk2(xv.w);
            const ulonglong2* ep = (const ulonglong2*)&es[c * ES + k0];
            ulonglong2 e0 = ep[0], e1 = ep[1], e2 = ep[2], e3 = ep[3];
            ull ee[8] = { e0.x, e0.y, e1.x, e1.y, e2.x, e2.y, e3.x, e3.y };
            #pragma unroll
            for (int j = 0; j < 8; j++) {
                fma2(acc[0][j], xd0, ee[j]);
                fma2(acc[1][j], xd1, ee[j]);
                fma2(acc[2][j], xd2, ee[j]);
                fma2(acc[3][j], xd3, ee[j]);
            }
        }
    }

    float o[4][16];
    #pragma unroll
    for (int p = 0; p < 4; p++)
        #pragma unroll
        for (int j = 0; j < 8; j++) upk(acc[p][j], o[p][2 * j], o[p][2 * j + 1]);

    if constexpr (EPI == 0) {
        float en[16];
        const float4* e4 = (const float4*)&EB[kg0 + k0];
        #pragma unroll
        for (int q = 0; q < 4; q++) {
            float4 v = e4[q];
            en[4 * q] = v.x; en[4 * q + 1] = v.y; en[4 * q + 2] = v.z; en[4 * q + 3] = v.w;
        }
        #pragma unroll
        for (int p = 0; p < 4; p++) {
            float xnp = XN[n0 + p0 + p];
            #pragma unroll
            for (int k = 0; k < 16; k++) o[p][k] = fmaf(-2.f, o[p][k], xnp + en[k]);
        }
    } else {
        float bs[16];
        const float4* b4 = (const float4*)&EB[kg0 + k0];
        #pragma unroll
        for (int q = 0; q < 4; q++) {
            float4 v = b4[q];
            bs[4 * q] = v.x; bs[4 * q + 1] = v.y; bs[4 * q + 2] = v.z; bs[4 * q + 3] = v.w;
        }
        #pragma unroll
        for (int p = 0; p < 4; p++)
            #pragma unroll
            for (int k = 0; k < 16; k++) {
                float v = o[p][k] + bs[k];
                if constexpr (EPI == 1) v = fmaxf(v, 0.f);
                o[p][k] = v;
            }
    }

    if constexpr (!OB) {
        #pragma unroll
        for (int p = 0; p < 4; p++) {
            float* r = OUT + (size_t)(n0 + p0 + p) * KTOT + kg0 + k0;
            #pragma unroll
            for (int q = 0; q < 4; q++)
                *(float4*)(r + 4 * q) =
                    make_float4(o[p][4 * q], o[p][4 * q + 1], o[p][4 * q + 2], o[p][4 * q + 3]);
        }
    } else {
        #pragma unroll
        for (int k = 0; k < 16; k++)
            *(float4*)&OUT[(size_t)(b * KTOT + kg0 + k0 + k) * HW + hw0 + p0] =
                make_float4(o[0][k], o[1][k], o[2][k], o[3][k]);
    }
}

// ---------------- row stats + q_feat + active-list export ----------------
template<int K, int C>
__global__ __launch_bounds__(256) void stats_kernel(
    const float* __restrict__ D, const float* __restrict__ E,
    float* __restrict__ QRAW, float* __restrict__ DMIN, float* __restrict__ IZ,
    int* __restrict__ ACTK, float* __restrict__ ACTW, int* __restrict__ CNT) {
    constexpr int PT = K / 256;
    constexpr int CQ = C / 32;
    int n = blockIdx.x, t = threadIdx.x;
    int wid = t >> 5, lane = t & 31;
    const float* dr = D + (size_t)n * K;
    float dv[PT];
    #pragma unroll
    for (int j = 0; j < PT; j++) dv[j] = dr[t + j * 256];

    float m = dv[0];
    #pragma unroll
    for (int j = 1; j < PT; j++) m = fminf(m, dv[j]);
    #pragma unroll
    for (int o = 16; o; o >>= 1) m = fminf(m, __shfl_xor_sync(0xffffffffu, m, o));

    __shared__ float smA[8], smB[8];
    __shared__ float qsm[8][C];
    __shared__ int s_cnt;
    if (t == 0) s_cnt = 0;
    if (lane == 0) smA[wid] = m;
    __syncthreads();
    m = smA[0];
    #pragma unroll
    for (int i = 1; i < 8; i++) m = fminf(m, smA[i]);

    float w[PT];
    float s = 0.f;
    #pragma unroll
    for (int j = 0; j < PT; j++) { w[j] = fexp((m - dv[j]) * 10.f); s += w[j]; }
    #pragma unroll
    for (int o = 16; o; o >>= 1) s += __shfl_xor_sync(0xffffffffu, s, o);
    if (lane == 0) smB[wid] = s;

    // export active (k, w) pairs
    #pragma unroll
    for (int j = 0; j < PT; j++) {
        if (w[j] != 0.f) {
            int idx = atomicAdd(&s_cnt, 1);
            if (idx < CAP) {
                ACTK[(size_t)n * CAP + idx] = t + j * 256;
                ACTW[(size_t)n * CAP + idx] = w[j];
            }
        }
    }

    // warp-cooperative q_feat accumulation
    float qr[CQ];
    #pragma unroll
    for (int q = 0; q < CQ; q++) qr[q] = 0.f;
    #pragma unroll
    for (int j = 0; j < PT; j++) {
        unsigned msk = __ballot_sync(0xffffffffu, w[j] != 0.f);
        while (msk) {
            int src = __ffs(msk) - 1;
            msk &= msk - 1;
            float ww = __shfl_sync(0xffffffffu, w[j], src);
            int kk = wid * 32 + src + j * 256;
            const float* er = E + (size_t)kk * C;
            #pragma unroll
            for (int q = 0; q < CQ; q++)
                qr[q] = fmaf(ww, er[q * 32 + lane], qr[q]);
        }
    }
    #pragma unroll
    for (int q = 0; q < CQ; q++) qsm[wid][q * 32 + lane] = qr[q];
    __syncthreads();

    float Z = smB[0];
    #pragma unroll
    for (int i = 1; i < 8; i++) Z += smB[i];
    float iz = 1.f / Z;
    if (t == 0) {
        DMIN[n] = m; IZ[n] = iz;
        CNT[n] = (s_cnt <= CAP) ? s_cnt : -1;   // -1 => fallback to d re-read
    }
    if (t < C) {
        float sum = 0.f;
        #pragma unroll
        for (int i = 0; i < 8; i++) sum += qsm[i][t];
        QRAW[(size_t)n * C + t] = sum * iz;
    }
}

// ---------------- assignment write from active lists (no d read on fast path) ----------------
template<int K>
__global__ __launch_bounds__(256) void akernel(
    const float* __restrict__ D, const int* __restrict__ ACTK,
    const float* __restrict__ ACTW, const int* __restrict__ CNT,
    float* __restrict__ A, const float* __restrict__ DMIN, const float* __restrict__ IZ) {
    int t = threadIdx.x;
    int kt = blockIdx.x, hwt = blockIdx.y, b = blockIdx.z;
    int n0 = b * HW + hwt * 32;
    int k0 = kt * 64;
    __shared__ float s[64 * 33];
    __shared__ float sm[32], si[32];
    __shared__ int scnt[32];
    #pragma unroll
    for (int i = 0; i < 9; i++) {
        int id = t + i * 256;
        if (id < 64 * 33) s[id] = 0.f;
    }
    if (t < 32) { sm[t] = DMIN[n0 + t]; si[t] = IZ[n0 + t]; scnt[t] = CNT[n0 + t]; }
    __syncthreads();

    // fast path: scatter actives into the tile
    {
        int r = t & 31, i0 = t >> 5;   // 8 slots per row
        int c = scnt[r];
        if (c > 0) {
            for (int i = i0; i < c; i += 8) {
                int k = ACTK[(size_t)(n0 + r) * CAP + i];
                if (k >= k0 && k < k0 + 64)
                    s[(k - k0) * 33 + r] = ACTW[(size_t)(n0 + r) * CAP + i] * si[r];
            }
        }
    }
    // fallback path: rows with overflowed lists recompute from d
    {
        int k = t & 63;
        #pragma unroll 1
        for (int rr = (t >> 6); rr < 32; rr += 4) {
            if (scnt[rr] < 0) {
                float d = D[(size_t)(n0 + rr) * K + k0 + k];
                s[k * 33 + rr] = fexp((sm[rr] - d) * 10.f) * si[rr];
            }
        }
    }
    __syncthreads();
    #pragma unroll
    for (int i = 0; i < 8; i++) {
        int id = t + i * 256;
        int k = id >> 5, r = id & 31;
        A[(size_t)(b * K + k0 + k) * HW + hwt * 32 + r] = s[k * 33 + r];
    }
}

// ---------------- gated mix + transpose ----------------
template<int C>
__global__ __launch_bounds__(256) void qmix_kernel(
    const float* __restrict__ QRAW, const float* __restrict__ X, float* __restrict__ QX) {
    __shared__ float tile[32][33];
    int t = threadIdx.x;
    int hw0 = blockIdx.x * 32, c0 = blockIdx.y * 32, b = blockIdx.z;
    int r = t >> 5, c = t & 31;
    #pragma unroll
    for (int i = 0; i < 4; i++) {
        int row = r + i * 8;
        tile[row][c] = QRAW[(size_t)(b * HW + hw0 + row) * C + c0 + c];
    }
    __syncthreads();
    float g = g_gate, og = 1.f - g;
    #pragma unroll
    for (int i = 0; i < 4; i++) {
        int ch = r + i * 8;
        size_t xi = ((size_t)(b * C + c0 + ch)) * HW + hw0 + c;
        QX[xi] = X[xi] * g + og * tile[c][ch];
    }
}

// ---------------- launcher (fork-join overlap) ----------------
extern "C" void kernel_launch(void* const* d_in, const int* in_sizes, int n_in,
                              void* d_out, int out_size) {
    const float* x0  = (const float*)d_in[0];
    const float* vq0 = (const float*)d_in[1];
    const float* vq1 = (const float*)d_in[2];
    const float* w1  = (const float*)d_in[3];
    const float* b1  = (const float*)d_in[4];
    const float* w2  = (const float*)d_in[5];
    const float* b2  = (const float*)d_in[6];
    const int*   cur = (const int*)d_in[7];

    float* out = (float*)d_out;
    float* x3  = out + OFF_X3;
    float* qx0 = out + OFF_QX0;
    float* qx3 = out + OFF_QX3;
    float* a0  = out + OFF_A0;
    float* a3  = out + OFF_A3;
    float* d0  = out + OFF_D0;
    float* d3  = out + OFF_D3;

    float *pxn0, *pxn3, *pen0, *pen1, *pdm0, *piz0, *pdm3, *piz3, *py1, *pq0;
    float *pactw0, *pactw1;
    int *pactk0, *pactk1, *pcnt0, *pcnt1;
    cudaGetSymbolAddress((void**)&pxn0, g_xn0);
    cudaGetSymbolAddress((void**)&pxn3, g_xn3);
    cudaGetSymbolAddress((void**)&pen0, g_en0);
    cudaGetSymbolAddress((void**)&pen1, g_en1);
    cudaGetSymbolAddress((void**)&pdm0, g_dm0);
    cudaGetSymbolAddress((void**)&piz0, g_iz0);
    cudaGetSymbolAddress((void**)&pdm3, g_dm3);
    cudaGetSymbolAddress((void**)&piz3, g_iz3);
    cudaGetSymbolAddress((void**)&py1,  g_y1);
    cudaGetSymbolAddress((void**)&pq0,  g_qraw0);
    cudaGetSymbolAddress((void**)&pactk0, g_actk0);
    cudaGetSymbolAddress((void**)&pactw0, g_actw0);
    cudaGetSymbolAddress((void**)&pcnt0, g_cnt0);
    cudaGetSymbolAddress((void**)&pactk1, g_actk1);
    cudaGetSymbolAddress((void**)&pactw1, g_actw1);
    cudaGetSymbolAddress((void**)&pcnt1, g_cnt1);

    static cudaStream_t sA = nullptr;
    static cudaEvent_t evF = nullptr, evP = nullptr, evS0 = nullptr, evS3 = nullptr, evJ = nullptr;
    if (sA == nullptr) {
        cudaStreamCreateWithFlags(&sA, cudaStreamNonBlocking);
        cudaEventCreateWithFlags(&evF,  cudaEventDisableTiming);
        cudaEventCreateWithFlags(&evP,  cudaEventDisableTiming);
        cudaEventCreateWithFlags(&evS0, cudaEventDisableTiming);
        cudaEventCreateWithFlags(&evS3, cudaEventDisableTiming);
        cudaEventCreateWithFlags(&evJ,  cudaEventDisableTiming);
    }

    // fork: prep on side stream, xnorm0 on main
    cudaEventRecord(evF, 0);
    cudaStreamWaitEvent(sA, evF, 0);
    prep_kernel<<<K0 + K1N, 64, 0, sA>>>(vq0, vq1, cur);
    cudaEventRecord(evP, sA);

    xnorm_kernel<C0><<<NPOS / 256, 256>>>(x0, pxn0);
    cudaStreamWaitEvent(0, evP, 0);

    // VQ0 distances -> d0
    gemm_kernel<64, 1, 0, 0, 2048><<<dim3(8, 800), 256>>>(x0, vq0, pxn0, pen0, d0);
    stats_kernel<2048, 64><<<NPOS, 256>>>(d0, vq0, pq0, pdm0, piz0, pactk0, pactw0, pcnt0);

    // fork: a0 write (from active lists) overlaps with qmix/head/dist3
    cudaEventRecord(evS0, 0);
    cudaStreamWaitEvent(sA, evS0, 0);
    akernel<2048><<<dim3(32, 50, 32), 256, 0, sA>>>(d0, pactk0, pactw0, pcnt0, a0, pdm0, piz0);

    qmix_kernel<64><<<dim3(50, 2, 32), 256>>>(pq0, x0, qx0);

    // head
    gemm_kernel<64, 1, 0, 1, 256><<<dim3(1, 800), 256>>>(qx0, w1, nullptr, b1, py1);
    gemm_kernel<256, 0, 1, 2, 256><<<dim3(1, 800), 256>>>(py1, w2, nullptr, b2, x3);

    // VQ1
    xnorm_kernel<C1><<<NPOS / 256, 256>>>(x3, pxn3);
    gemm_kernel<256, 1, 0, 0, 512><<<dim3(2, 800), 256>>>(x3, vq1, pxn3, pen1, d3);
    stats_kernel<512, 256><<<NPOS, 256>>>(d3, vq1, py1, pdm3, piz3, pactk1, pactw1, pcnt1);

    // fork: a3 overlaps with qmix3
    cudaEventRecord(evS3, 0);
    cudaStreamWaitEvent(sA, evS3, 0);
    akernel<512><<<dim3(8, 50, 32), 256, 0, sA>>>(d3, pactk1, pactw1, pcnt1, a3, pdm3, piz3);

    qmix_kernel<256><<<dim3(50, 8, 32), 256>>>(py1, x3, qx3);

    // join
    cudaEventRecord(evJ, sA);
    cudaStreamWaitEvent(0, evJ, 0);
}

// round 16
// speedup vs baseline: 1.0426x; 1.0426x over previous
#include <cuda_runtime.h>

typedef unsigned long long ull;

#define DEV __device__ __forceinline__

DEV ull pk2(float x) { ull r; asm("mov.b64 %0, {%1, %1};" : "=l"(r) : "f"(x)); return r; }
DEV void upk(ull v, float& a, float& b) { asm("mov.b64 {%0, %1}, %2;" : "=f"(a), "=f"(b) : "l"(v)); }
DEV void fma2(ull& d, ull a, ull b) { asm("fma.rn.f32x2 %0, %1, %2, %0;" : "+l"(d) : "l"(a), "l"(b)); }

// fast exp on the FMA pipe (no MUFU). exp(a) for a <= 0; exact 0 below -87.
DEV float fexp(float a) {
    const float L2E = 1.4426950408889634f;
    float z = fmaf(a, L2E, 12582912.0f);
    int   i = __float_as_int(z);
    float nf = z - 12582912.0f;
    float f = fmaf(a, L2E, -nf);
    float p =           1.3333558146e-3f;
    p = fmaf(p, f,      9.6181291076e-3f);
    p = fmaf(p, f,      5.5504108664e-2f);
    p = fmaf(p, f,      2.4022650696e-1f);
    p = fmaf(p, f,      6.9314718056e-1f);
    p = fmaf(p, f,      1.0f);
    float s = __int_as_float((i - 1262485377) << 23);
    float r = s * p;
    return a > -87.0f ? r : 0.0f;
}

// ---------------- problem constants ----------------
constexpr int HW   = 1600;
constexpr int NPOS = 51200;
constexpr int C0   = 64;
constexpr int K0   = 2048;
constexpr int C1   = 256;
constexpr int K1N  = 512;

constexpr size_t OFF_X3  = 0;
constexpr size_t OFF_QX0 = 13107200;
constexpr size_t OFF_QX3 = 16384000;
constexpr size_t OFF_A0  = 29491200;
constexpr size_t OFF_A3  = 134348800;
constexpr size_t OFF_D0  = 160563200;
constexpr size_t OFF_D3  = 265420800;

// ---------------- scratch ----------------
__device__ __align__(16) float g_xn0[NPOS];
__device__ __align__(16) float g_xn3[NPOS];
__device__ __align__(16) float g_en0[K0];
__device__ __align__(16) float g_en1[K1N];
__device__ __align__(16) float g_dm0[NPOS];
__device__ __align__(16) float g_iz0[NPOS];
__device__ __align__(16) float g_dm3[NPOS];
__device__ __align__(16) float g_iz3[NPOS];
__device__ float g_gate;
__device__ __align__(16) float g_y1[(size_t)NPOS * C1];     // head hidden, later reused as qraw3
__device__ __align__(16) float g_qraw0[(size_t)NPOS * C0];

// ---------------- prep: codebook row norms + gate ----------------
__global__ void prep_kernel(const float* __restrict__ vq0, const float* __restrict__ vq1,
                            const int* __restrict__ cur) {
    int bid = blockIdx.x, t = threadIdx.x;
    if (bid == 0 && t == 0) {
        int ci = *cur;
        float gg = (10000 - ci) / 10000.f;
        g_gate = gg > 0.f ? gg : 0.f;
    }
    float s = 0.f;
    if (bid < K0) {
        float v = vq0[bid * 64 + t];
        s = v * v;
    } else {
        int r = bid - K0;
        #pragma unroll
        for (int i = 0; i < 4; i++) { float v = vq1[r * 256 + i * 64 + t]; s += v * v; }
    }
    #pragma unroll
    for (int o = 16; o; o >>= 1) s += __shfl_xor_sync(0xffffffffu, s, o);
    __shared__ float sm[2];
    if ((t & 31) == 0) sm[t >> 5] = s;
    __syncthreads();
    if (t == 0) {
        float r = sm[0] + sm[1];
        if (bid < K0) g_en0[bid] = r; else g_en1[bid - K0] = r;
    }
}

// ---------------- per-position squared norms (X in BCHW) ----------------
template<int C>
__global__ void xnorm_kernel(const float* __restrict__ X, float* __restrict__ out) {
    int n = blockIdx.x * 256 + threadIdx.x;
    int b = n / HW, hw = n % HW;
    const float* p = X + (size_t)b * C * HW + hw;
    float s = 0.f;
    #pragma unroll 8
    for (int c = 0; c < C; c++) { float v = p[(size_t)c * HW]; s += v * v; }
    out[n] = s;
}

// ---------------- generic FFMA2 GEMM (R8 proven body) ----------------
template<int CDIM, int XB, int OB, int EPI, int KTOT>
__global__ __launch_bounds__(256) void gemm_kernel(
    const float* __restrict__ X, const float* __restrict__ E,
    const float* __restrict__ XN, const float* __restrict__ EB,
    float* __restrict__ OUT) {
    constexpr int XS = 68, ES = 260;
    __shared__ __align__(16) float xs[16 * XS];
    __shared__ __align__(16) float es[16 * ES];
    int t = threadIdx.x;
    int p0 = (t & 15) * 4, k0 = (t >> 4) * 16;
    int pt = blockIdx.y;
    int kg0 = blockIdx.x * 256;
    int b = pt / 25, hw0 = (pt % 25) * 64;
    int n0 = pt * 64;
    size_t xbase = XB ? ((size_t)b * CDIM * HW + hw0) : ((size_t)n0 * CDIM);

    ull acc[4][8];
    #pragma unroll
    for (int p = 0; p < 4; p++)
        #pragma unroll
        for (int j = 0; j < 8; j++) acc[p][j] = 0ull;

    #pragma unroll 1
    for (int cc = 0; cc < CDIM; cc += 16) {
        __syncthreads();
        #pragma unroll
        for (int i = 0; i < 4; i++) {
            int id = t + i * 256;
            if (XB) {
                int c = id >> 6, p = id & 63;
                xs[c * XS + p] = X[xbase + (size_t)(cc + c) * HW + p];
            } else {
                int p = id >> 4, c = id & 15;
                xs[c * XS + p] = X[xbase + (size_t)p * CDIM + cc + c];
            }
        }
        #pragma unroll
        for (int i = 0; i < 16; i++) {
            int id = t + i * 256;
            int k = id >> 4, c = id & 15;
            es[c * ES + k] = E[(size_t)(kg0 + k) * CDIM + cc + c];
        }
        __syncthreads();
        #pragma unroll
        for (int c = 0; c < 16; c++) {
            float4 xv = *(const float4*)&xs[c * XS + p0];
            ull xd0 = pk2(xv.x), xd1 = pk2(xv.y), xd2 = pk2(xv.z), xd3 = pk2(xv.w);
            const ulonglong2* ep = (const ulonglong2*)&es[c * ES + k0];
            ulonglong2 e0 = ep[0], e1 = ep[1], e2 = ep[2], e3 = ep[3];
            ull ee[8] = { e0.x, e0.y, e1.x, e1.y, e2.x, e2.y, e3.x, e3.y };
            #pragma unroll
            for (int j = 0; j < 8; j++) {
                fma2(acc[0][j], xd0, ee[j]);
                fma2(acc[1][j], xd1, ee[j]);
                fma2(acc[2][j], xd2, ee[j]);
                fma2(acc[3][j], xd3, ee[j]);
            }
        }
    }

    float o[4][16];
    #pragma unroll
    for (int p = 0; p < 4; p++)
        #pragma unroll
        for (int j = 0; j < 8; j++) upk(acc[p][j], o[p][2 * j], o[p][2 * j + 1]);

    if constexpr (EPI == 0) {
        float en[16];
        const float4* e4 = (const float4*)&EB[kg0 + k0];
        #pragma unroll
        for (int q = 0; q < 4; q++) {
            float4 v = e4[q];
            en[4 * q] = v.x; en[4 * q + 1] = v.y; en[4 * q + 2] = v.z; en[4 * q + 3] = v.w;
        }
        #pragma unroll
        for (int p = 0; p < 4; p++) {
            float xnp = XN[n0 + p0 + p];
            #pragma unroll
            for (int k = 0; k < 16; k++) o[p][k] = fmaf(-2.f, o[p][k], xnp + en[k]);
        }
    } else {
        float bs[16];
        const float4* b4 = (const float4*)&EB[kg0 + k0];
        #pragma unroll
        for (int q = 0; q < 4; q++) {
            float4 v = b4[q];
            bs[4 * q] = v.x; bs[4 * q + 1] = v.y; bs[4 * q + 2] = v.z; bs[4 * q + 3] = v.w;
        }
        #pragma unroll
        for (int p = 0; p < 4; p++)
            #pragma unroll
            for (int k = 0; k < 16; k++) {
                float v = o[p][k] + bs[k];
                if constexpr (EPI == 1) v = fmaxf(v, 0.f);
                o[p][k] = v;
            }
    }

    if constexpr (!OB) {
        #pragma unroll
        for (int p = 0; p < 4; p++) {
            float* r = OUT + (size_t)(n0 + p0 + p) * KTOT + kg0 + k0;
            #pragma unroll
            for (int q = 0; q < 4; q++)
                *(float4*)(r + 4 * q) =
                    make_float4(o[p][4 * q], o[p][4 * q + 1], o[p][4 * q + 2], o[p][4 * q + 3]);
        }
    } else {
        #pragma unroll
        for (int k = 0; k < 16; k++)
            *(float4*)&OUT[(size_t)(b * KTOT + kg0 + k0 + k) * HW + hw0 + p0] =
                make_float4(o[0][k], o[1][k], o[2][k], o[3][k]);
    }
}

// ---------------- row stats + warp-cooperative q_feat (R11 proven body + nbase) ----------------
template<int K, int C>
__global__ __launch_bounds__(256) void stats_kernel(
    const float* __restrict__ D, const float* __restrict__ E,
    float* __restrict__ QRAW, float* __restrict__ DMIN, float* __restrict__ IZ,
    int nbase) {
    constexpr int PT = K / 256;
    constexpr int CQ = C / 32;
    int n = nbase + blockIdx.x, t = threadIdx.x;
    int wid = t >> 5, lane = t & 31;
    const float* dr = D + (size_t)n * K;
    float dv[PT];
    #pragma unroll
    for (int j = 0; j < PT; j++) dv[j] = dr[t + j * 256];

    float m = dv[0];
    #pragma unroll
    for (int j = 1; j < PT; j++) m = fminf(m, dv[j]);
    #pragma unroll
    for (int o = 16; o; o >>= 1) m = fminf(m, __shfl_xor_sync(0xffffffffu, m, o));

    __shared__ float smA[8], smB[8];
    __shared__ float qsm[8][C];
    if (lane == 0) smA[wid] = m;
    __syncthreads();
    m = smA[0];
    #pragma unroll
    for (int i = 1; i < 8; i++) m = fminf(m, smA[i]);

    float w[PT];
    float s = 0.f;
    #pragma unroll
    for (int j = 0; j < PT; j++) { w[j] = fexp((m - dv[j]) * 10.f); s += w[j]; }
    #pragma unroll
    for (int o = 16; o; o >>= 1) s += __shfl_xor_sync(0xffffffffu, s, o);
    if (lane == 0) smB[wid] = s;

    float qr[CQ];
    #pragma unroll
    for (int q = 0; q < CQ; q++) qr[q] = 0.f;
    #pragma unroll
    for (int j = 0; j < PT; j++) {
        unsigned msk = __ballot_sync(0xffffffffu, w[j] != 0.f);
        while (msk) {
            int src = __ffs(msk) - 1;
            msk &= msk - 1;
            float ww = __shfl_sync(0xffffffffu, w[j], src);
            int kk = wid * 32 + src + j * 256;
            const float* er = E + (size_t)kk * C;
            #pragma unroll
            for (int q = 0; q < CQ; q++)
                qr[q] = fmaf(ww, er[q * 32 + lane], qr[q]);
        }
    }
    #pragma unroll
    for (int q = 0; q < CQ; q++) qsm[wid][q * 32 + lane] = qr[q];
    __syncthreads();

    float Z = smB[0];
    #pragma unroll
    for (int i = 1; i < 8; i++) Z += smB[i];
    float iz = 1.f / Z;
    if (t == 0) { DMIN[n] = m; IZ[n] = iz; }
    if (t < C) {
        float sum = 0.f;
        #pragma unroll
        for (int i = 0; i < 8; i++) sum += qsm[i][t];
        QRAW[(size_t)n * C + t] = sum * iz;
    }
}

// ---------------- gated mix + transpose ----------------
template<int C>
__global__ __launch_bounds__(256) void qmix_kernel(
    const float* __restrict__ QRAW, const float* __restrict__ X, float* __restrict__ QX) {
    __shared__ float tile[32][33];
    int t = threadIdx.x;
    int hw0 = blockIdx.x * 32, c0 = blockIdx.y * 32, b = blockIdx.z;
    int r = t >> 5, c = t & 31;
    #pragma unroll
    for (int i = 0; i < 4; i++) {
        int row = r + i * 8;
        tile[row][c] = QRAW[(size_t)(b * HW + hw0 + row) * C + c0 + c];
    }
    __syncthreads();
    float g = g_gate, og = 1.f - g;
    #pragma unroll
    for (int i = 0; i < 4; i++) {
        int ch = r + i * 8;
        size_t xi = ((size_t)(b * C + c0 + ch)) * HW + hw0 + c;
        QX[xi] = X[xi] * g + og * tile[c][ch];
    }
}

// ---------------- assignment write (R12 proven float4+skip body + bbase) ----------------
template<int K>
__global__ __launch_bounds__(256) void awrite_kernel(
    const float* __restrict__ D, float* __restrict__ A,
    const float* __restrict__ DMIN, const float* __restrict__ IZ, int bbase) {
    int t = threadIdx.x;
    int kt = blockIdx.x, hwt = blockIdx.y, b = bbase + blockIdx.z;
    int n0 = b * HW + hwt * 32;
    int k0 = kt * 64;
    __shared__ float s[64 * 33];
    __shared__ float sm[32], si[32];
    if (t < 32) { sm[t] = DMIN[n0 + t]; si[t] = IZ[n0 + t]; }
    __syncthreads();
    #pragma unroll
    for (int i = 0; i < 2; i++) {
        int q = t + i * 256;
        int r = q >> 4, kq = (q & 15) * 4;
        float4 d4 = *(const float4*)&D[(size_t)(n0 + r) * K + k0 + kq];
        float mr = sm[r];
        float e0 = (mr - d4.x) * 10.f, e1 = (mr - d4.y) * 10.f;
        float e2 = (mr - d4.z) * 10.f, e3 = (mr - d4.w) * 10.f;
        float mx = fmaxf(fmaxf(e0, e1), fmaxf(e2, e3));
        float v0 = 0.f, v1 = 0.f, v2 = 0.f, v3 = 0.f;
        if (__ballot_sync(0xffffffffu, mx > -87.f)) {
            float sr = si[r];
            v0 = fexp(e0) * sr; v1 = fexp(e1) * sr;
            v2 = fexp(e2) * sr; v3 = fexp(e3) * sr;
        }
        s[(kq + 0) * 33 + r] = v0;
        s[(kq + 1) * 33 + r] = v1;
        s[(kq + 2) * 33 + r] = v2;
        s[(kq + 3) * 33 + r] = v3;
    }
    __syncthreads();
    #pragma unroll
    for (int i = 0; i < 8; i++) {
        int id = t + i * 256;
        int k = id >> 5, r = id & 31;
        A[(size_t)(b * K + k0 + k) * HW + hwt * 32 + r] = s[k * 33 + r];
    }
}

// ---------------- launcher: chunked stats->awrite pipeline for L2 reuse ----------------
extern "C" void kernel_launch(void* const* d_in, const int* in_sizes, int n_in,
                              void* d_out, int out_size) {
    const float* x0  = (const float*)d_in[0];
    const float* vq0 = (const float*)d_in[1];
    const float* vq1 = (const float*)d_in[2];
    const float* w1  = (const float*)d_in[3];
    const float* b1  = (const float*)d_in[4];
    const float* w2  = (const float*)d_in[5];
    const float* b2  = (const float*)d_in[6];
    const int*   cur = (const int*)d_in[7];

    float* out = (float*)d_out;
    float* x3  = out + OFF_X3;
    float* qx0 = out + OFF_QX0;
    float* qx3 = out + OFF_QX3;
    float* a0  = out + OFF_A0;
    float* a3  = out + OFF_A3;
    float* d0  = out + OFF_D0;
    float* d3  = out + OFF_D3;

    float *pxn0, *pxn3, *pen0, *pen1, *pdm0, *piz0, *pdm3, *piz3, *py1, *pq0;
    cudaGetSymbolAddress((void**)&pxn0, g_xn0);
    cudaGetSymbolAddress((void**)&pxn3, g_xn3);
    cudaGetSymbolAddress((void**)&pen0, g_en0);
    cudaGetSymbolAddress((void**)&pen1, g_en1);
    cudaGetSymbolAddress((void**)&pdm0, g_dm0);
    cudaGetSymbolAddress((void**)&piz0, g_iz0);
    cudaGetSymbolAddress((void**)&pdm3, g_dm3);
    cudaGetSymbolAddress((void**)&piz3, g_iz3);
    cudaGetSymbolAddress((void**)&py1,  g_y1);
    cudaGetSymbolAddress((void**)&pq0,  g_qraw0);

    static cudaStream_t sA = nullptr;
    static cudaEvent_t evF = nullptr, evP = nullptr, evJ = nullptr;
    static cudaEvent_t evC0[8] = {}, evC3[4] = {};
    if (sA == nullptr) {
        cudaStreamCreateWithFlags(&sA, cudaStreamNonBlocking);
        cudaEventCreateWithFlags(&evF, cudaEventDisableTiming);
        cudaEventCreateWithFlags(&evP, cudaEventDisableTiming);
        cudaEventCreateWithFlags(&evJ, cudaEventDisableTiming);
        for (int i = 0; i < 8; i++) cudaEventCreateWithFlags(&evC0[i], cudaEventDisableTiming);
        for (int i = 0; i < 4; i++) cudaEventCreateWithFlags(&evC3[i], cudaEventDisableTiming);
    }

    // fork: prep on side stream, xnorm0 on main
    cudaEventRecord(evF, 0);
    cudaStreamWaitEvent(sA, evF, 0);
    prep_kernel<<<K0 + K1N, 64, 0, sA>>>(vq0, vq1, cur);
    cudaEventRecord(evP, sA);

    xnorm_kernel<C0><<<NPOS / 256, 256>>>(x0, pxn0);
    cudaStreamWaitEvent(0, evP, 0);

    // VQ0 distances -> d0
    gemm_kernel<64, 1, 0, 0, 2048><<<dim3(8, 800), 256>>>(x0, vq0, pxn0, pen0, d0);

    // chunked stats (main) -> awrite (side, L2-resident rows): 8 chunks x 4 batches
    for (int c = 0; c < 8; c++) {
        stats_kernel<2048, 64><<<6400, 256>>>(d0, vq0, pq0, pdm0, piz0, c * 6400);
        cudaEventRecord(evC0[c], 0);
        cudaStreamWaitEvent(sA, evC0[c], 0);
        awrite_kernel<2048><<<dim3(32, 50, 4), 256, 0, sA>>>(d0, a0, pdm0, piz0, c * 4);
    }

    qmix_kernel<64><<<dim3(50, 2, 32), 256>>>(pq0, x0, qx0);

    // head
    gemm_kernel<64, 1, 0, 1, 256><<<dim3(1, 800), 256>>>(qx0, w1, nullptr, b1, py1);
    gemm_kernel<256, 0, 1, 2, 256><<<dim3(1, 800), 256>>>(py1, w2, nullptr, b2, x3);

    // VQ1
    xnorm_kernel<C1><<<NPOS / 256, 256>>>(x3, pxn3);
    gemm_kernel<256, 1, 0, 0, 512><<<dim3(2, 800), 256>>>(x3, vq1, pxn3, pen1, d3);

    // chunked stats -> awrite for level 3: 4 chunks x 8 batches
    for (int c = 0; c < 4; c++) {
        stats_kernel<512, 256><<<12800, 256>>>(d3, vq1, py1, pdm3, piz3, c * 12800);
        cudaEventRecord(evC3[c], 0);
        cudaStreamWaitEvent(sA, evC3[c], 0);
        awrite_kernel<512><<<dim3(8, 50, 8), 256, 0, sA>>>(d3, a3, pdm3, piz3, c * 8);
    }

    qmix_kernel<256><<<dim3(50, 8, 32), 256>>>(py1, x3, qx3);

    // join
    cudaEventRecord(evJ, sA);
    cudaStreamWaitEvent(0, evJ, 0);
}

// round 17
// speedup vs baseline: 1.0621x; 1.0187x over previous
#include <cuda_runtime.h>

typedef unsigned long long ull;

#define DEV __device__ __forceinline__

DEV ull pk2(float x) { ull r; asm("mov.b64 %0, {%1, %1};" : "=l"(r) : "f"(x)); return r; }
DEV void upk(ull v, float& a, float& b) { asm("mov.b64 {%0, %1}, %2;" : "=f"(a), "=f"(b) : "l"(v)); }
DEV void fma2(ull& d, ull a, ull b) { asm("fma.rn.f32x2 %0, %1, %2, %0;" : "+l"(d) : "l"(a), "l"(b)); }

// fast exp on the FMA pipe (no MUFU). exp(a) for a <= 0; exact 0 below -87.
DEV float fexp(float a) {
    const float L2E = 1.4426950408889634f;
    float z = fmaf(a, L2E, 12582912.0f);
    int   i = __float_as_int(z);
    float nf = z - 12582912.0f;
    float f = fmaf(a, L2E, -nf);
    float p =           1.3333558146e-3f;
    p = fmaf(p, f,      9.6181291076e-3f);
    p = fmaf(p, f,      5.5504108664e-2f);
    p = fmaf(p, f,      2.4022650696e-1f);
    p = fmaf(p, f,      6.9314718056e-1f);
    p = fmaf(p, f,      1.0f);
    float s = __int_as_float((i - 1262485377) << 23);
    float r = s * p;
    return a > -87.0f ? r : 0.0f;
}

// ---------------- problem constants ----------------
constexpr int HW   = 1600;
constexpr int NPOS = 51200;
constexpr int C0   = 64;
constexpr int K0   = 2048;
constexpr int C1   = 256;
constexpr int K1N  = 512;

constexpr size_t OFF_X3  = 0;
constexpr size_t OFF_QX0 = 13107200;
constexpr size_t OFF_QX3 = 16384000;
constexpr size_t OFF_A0  = 29491200;
constexpr size_t OFF_A3  = 134348800;
constexpr size_t OFF_D0  = 160563200;
constexpr size_t OFF_D3  = 265420800;

// ---------------- scratch ----------------
__device__ __align__(16) float g_xn0[NPOS];
__device__ __align__(16) float g_xn3[NPOS];
__device__ __align__(16) float g_en0[K0];
__device__ __align__(16) float g_en1[K1N];
__device__ __align__(16) float g_dm0[NPOS];
__device__ __align__(16) float g_iz0[NPOS];
__device__ __align__(16) float g_dm3[NPOS];
__device__ __align__(16) float g_iz3[NPOS];
__device__ float g_gate;
__device__ __align__(16) float g_y1[(size_t)NPOS * C1];     // head hidden, later reused as qraw3
__device__ __align__(16) float g_qraw0[(size_t)NPOS * C0];

// ---------------- prep: codebook row norms + gate ----------------
__global__ void prep_kernel(const float* __restrict__ vq0, const float* __restrict__ vq1,
                            const int* __restrict__ cur) {
    int bid = blockIdx.x, t = threadIdx.x;
    if (bid == 0 && t == 0) {
        int ci = *cur;
        float gg = (10000 - ci) / 10000.f;
        g_gate = gg > 0.f ? gg : 0.f;
    }
    float s = 0.f;
    if (bid < K0) {
        float v = vq0[bid * 64 + t];
        s = v * v;
    } else {
        int r = bid - K0;
        #pragma unroll
        for (int i = 0; i < 4; i++) { float v = vq1[r * 256 + i * 64 + t]; s += v * v; }
    }
    #pragma unroll
    for (int o = 16; o; o >>= 1) s += __shfl_xor_sync(0xffffffffu, s, o);
    __shared__ float sm[2];
    if ((t & 31) == 0) sm[t >> 5] = s;
    __syncthreads();
    if (t == 0) {
        float r = sm[0] + sm[1];
        if (bid < K0) g_en0[bid] = r; else g_en1[bid - K0] = r;
    }
}

// ---------------- per-position squared norms (X in BCHW) ----------------
template<int C>
__global__ void xnorm_kernel(const float* __restrict__ X, float* __restrict__ out) {
    int n = blockIdx.x * 256 + threadIdx.x;
    int b = n / HW, hw = n % HW;
    const float* p = X + (size_t)b * C * HW + hw;
    float s = 0.f;
    #pragma unroll 8
    for (int c = 0; c < C; c++) { float v = p[(size_t)c * HW]; s += v * v; }
    out[n] = s;
}

// ---------------- generic FFMA2 GEMM (R8 proven body + yofs) ----------------
template<int CDIM, int XB, int OB, int EPI, int KTOT>
__global__ __launch_bounds__(256) void gemm_kernel(
    const float* __restrict__ X, const float* __restrict__ E,
    const float* __restrict__ XN, const float* __restrict__ EB,
    float* __restrict__ OUT, int yofs) {
    constexpr int XS = 68, ES = 260;
    __shared__ __align__(16) float xs[16 * XS];
    __shared__ __align__(16) float es[16 * ES];
    int t = threadIdx.x;
    int p0 = (t & 15) * 4, k0 = (t >> 4) * 16;
    int pt = yofs + blockIdx.y;
    int kg0 = blockIdx.x * 256;
    int b = pt / 25, hw0 = (pt % 25) * 64;
    int n0 = pt * 64;
    size_t xbase = XB ? ((size_t)b * CDIM * HW + hw0) : ((size_t)n0 * CDIM);

    ull acc[4][8];
    #pragma unroll
    for (int p = 0; p < 4; p++)
        #pragma unroll
        for (int j = 0; j < 8; j++) acc[p][j] = 0ull;

    #pragma unroll 1
    for (int cc = 0; cc < CDIM; cc += 16) {
        __syncthreads();
        #pragma unroll
        for (int i = 0; i < 4; i++) {
            int id = t + i * 256;
            if (XB) {
                int c = id >> 6, p = id & 63;
                xs[c * XS + p] = X[xbase + (size_t)(cc + c) * HW + p];
            } else {
                int p = id >> 4, c = id & 15;
                xs[c * XS + p] = X[xbase + (size_t)p * CDIM + cc + c];
            }
        }
        #pragma unroll
        for (int i = 0; i < 16; i++) {
            int id = t + i * 256;
            int k = id >> 4, c = id & 15;
            es[c * ES + k] = E[(size_t)(kg0 + k) * CDIM + cc + c];
        }
        __syncthreads();
        #pragma unroll
        for (int c = 0; c < 16; c++) {
            float4 xv = *(const float4*)&xs[c * XS + p0];
            ull xd0 = pk2(xv.x), xd1 = pk2(xv.y), xd2 = pk2(xv.z), xd3 = pk2(xv.w);
            const ulonglong2* ep = (const ulonglong2*)&es[c * ES + k0];
            ulonglong2 e0 = ep[0], e1 = ep[1], e2 = ep[2], e3 = ep[3];
            ull ee[8] = { e0.x, e0.y, e1.x, e1.y, e2.x, e2.y, e3.x, e3.y };
            #pragma unroll
            for (int j = 0; j < 8; j++) {
                fma2(acc[0][j], xd0, ee[j]);
                fma2(acc[1][j], xd1, ee[j]);
                fma2(acc[2][j], xd2, ee[j]);
                fma2(acc[3][j], xd3, ee[j]);
            }
        }
    }

    float o[4][16];
    #pragma unroll
    for (int p = 0; p < 4; p++)
        #pragma unroll
        for (int j = 0; j < 8; j++) upk(acc[p][j], o[p][2 * j], o[p][2 * j + 1]);

    if constexpr (EPI == 0) {
        float en[16];
        const float4* e4 = (const float4*)&EB[kg0 + k0];
        #pragma unroll
        for (int q = 0; q < 4; q++) {
            float4 v = e4[q];
            en[4 * q] = v.x; en[4 * q + 1] = v.y; en[4 * q + 2] = v.z; en[4 * q + 3] = v.w;
        }
        #pragma unroll
        for (int p = 0; p < 4; p++) {
            float xnp = XN[n0 + p0 + p];
            #pragma unroll
            for (int k = 0; k < 16; k++) o[p][k] = fmaf(-2.f, o[p][k], xnp + en[k]);
        }
    } else {
        float bs[16];
        const float4* b4 = (const float4*)&EB[kg0 + k0];
        #pragma unroll
        for (int q = 0; q < 4; q++) {
            float4 v = b4[q];
            bs[4 * q] = v.x; bs[4 * q + 1] = v.y; bs[4 * q + 2] = v.z; bs[4 * q + 3] = v.w;
        }
        #pragma unroll
        for (int p = 0; p < 4; p++)
            #pragma unroll
            for (int k = 0; k < 16; k++) {
                float v = o[p][k] + bs[k];
                if constexpr (EPI == 1) v = fmaxf(v, 0.f);
                o[p][k] = v;
            }
    }

    if constexpr (!OB) {
        #pragma unroll
        for (int p = 0; p < 4; p++) {
            float* r = OUT + (size_t)(n0 + p0 + p) * KTOT + kg0 + k0;
            #pragma unroll
            for (int q = 0; q < 4; q++)
                *(float4*)(r + 4 * q) =
                    make_float4(o[p][4 * q], o[p][4 * q + 1], o[p][4 * q + 2], o[p][4 * q + 3]);
        }
    } else {
        #pragma unroll
        for (int k = 0; k < 16; k++)
            *(float4*)&OUT[(size_t)(b * KTOT + kg0 + k0 + k) * HW + hw0 + p0] =
                make_float4(o[0][k], o[1][k], o[2][k], o[3][k]);
    }
}

// ---------------- row stats + warp-cooperative q_feat (R11 proven body + nbase) ----------------
template<int K, int C>
__global__ __launch_bounds__(256) void stats_kernel(
    const float* __restrict__ D, const float* __restrict__ E,
    float* __restrict__ QRAW, float* __restrict__ DMIN, float* __restrict__ IZ,
    int nbase) {
    constexpr int PT = K / 256;
    constexpr int CQ = C / 32;
    int n = nbase + blockIdx.x, t = threadIdx.x;
    int wid = t >> 5, lane = t & 31;
    const float* dr = D + (size_t)n * K;
    float dv[PT];
    #pragma unroll
    for (int j = 0; j < PT; j++) dv[j] = dr[t + j * 256];

    float m = dv[0];
    #pragma unroll
    for (int j = 1; j < PT; j++) m = fminf(m, dv[j]);
    #pragma unroll
    for (int o = 16; o; o >>= 1) m = fminf(m, __shfl_xor_sync(0xffffffffu, m, o));

    __shared__ float smA[8], smB[8];
    __shared__ float qsm[8][C];
    if (lane == 0) smA[wid] = m;
    __syncthreads();
    m = smA[0];
    #pragma unroll
    for (int i = 1; i < 8; i++) m = fminf(m, smA[i]);

    float w[PT];
    float s = 0.f;
    #pragma unroll
    for (int j = 0; j < PT; j++) { w[j] = fexp((m - dv[j]) * 10.f); s += w[j]; }
    #pragma unroll
    for (int o = 16; o; o >>= 1) s += __shfl_xor_sync(0xffffffffu, s, o);
    if (lane == 0) smB[wid] = s;

    float qr[CQ];
    #pragma unroll
    for (int q = 0; q < CQ; q++) qr[q] = 0.f;
    #pragma unroll
    for (int j = 0; j < PT; j++) {
        unsigned msk = __ballot_sync(0xffffffffu, w[j] != 0.f);
        while (msk) {
            int src = __ffs(msk) - 1;
            msk &= msk - 1;
            float ww = __shfl_sync(0xffffffffu, w[j], src);
            int kk = wid * 32 + src + j * 256;
            const float* er = E + (size_t)kk * C;
            #pragma unroll
            for (int q = 0; q < CQ; q++)
                qr[q] = fmaf(ww, er[q * 32 + lane], qr[q]);
        }
    }
    #pragma unroll
    for (int q = 0; q < CQ; q++) qsm[wid][q * 32 + lane] = qr[q];
    __syncthreads();

    float Z = smB[0];
    #pragma unroll
    for (int i = 1; i < 8; i++) Z += smB[i];
    float iz = 1.f / Z;
    if (t == 0) { DMIN[n] = m; IZ[n] = iz; }
    if (t < C) {
        float sum = 0.f;
        #pragma unroll
        for (int i = 0; i < 8; i++) sum += qsm[i][t];
        QRAW[(size_t)n * C + t] = sum * iz;
    }
}

// ---------------- gated mix + transpose ----------------
template<int C>
__global__ __launch_bounds__(256) void qmix_kernel(
    const float* __restrict__ QRAW, const float* __restrict__ X, float* __restrict__ QX) {
    __shared__ float tile[32][33];
    int t = threadIdx.x;
    int hw0 = blockIdx.x * 32, c0 = blockIdx.y * 32, b = blockIdx.z;
    int r = t >> 5, c = t & 31;
    #pragma unroll
    for (int i = 0; i < 4; i++) {
        int row = r + i * 8;
        tile[row][c] = QRAW[(size_t)(b * HW + hw0 + row) * C + c0 + c];
    }
    __syncthreads();
    float g = g_gate, og = 1.f - g;
    #pragma unroll
    for (int i = 0; i < 4; i++) {
        int ch = r + i * 8;
        size_t xi = ((size_t)(b * C + c0 + ch)) * HW + hw0 + c;
        QX[xi] = X[xi] * g + og * tile[c][ch];
    }
}

// ---------------- assignment write (R12 proven float4+skip body + bbase) ----------------
template<int K>
__global__ __launch_bounds__(256) void awrite_kernel(
    const float* __restrict__ D, float* __restrict__ A,
    const float* __restrict__ DMIN, const float* __restrict__ IZ, int bbase) {
    int t = threadIdx.x;
    int kt = blockIdx.x, hwt = blockIdx.y, b = bbase + blockIdx.z;
    int n0 = b * HW + hwt * 32;
    int k0 = kt * 64;
    __shared__ float s[64 * 33];
    __shared__ float sm[32], si[32];
    if (t < 32) { sm[t] = DMIN[n0 + t]; si[t] = IZ[n0 + t]; }
    __syncthreads();
    #pragma unroll
    for (int i = 0; i < 2; i++) {
        int q = t + i * 256;
        int r = q >> 4, kq = (q & 15) * 4;
        float4 d4 = *(const float4*)&D[(size_t)(n0 + r) * K + k0 + kq];
        float mr = sm[r];
        float e0 = (mr - d4.x) * 10.f, e1 = (mr - d4.y) * 10.f;
        float e2 = (mr - d4.z) * 10.f, e3 = (mr - d4.w) * 10.f;
        float mx = fmaxf(fmaxf(e0, e1), fmaxf(e2, e3));
        float v0 = 0.f, v1 = 0.f, v2 = 0.f, v3 = 0.f;
        if (__ballot_sync(0xffffffffu, mx > -87.f)) {
            float sr = si[r];
            v0 = fexp(e0) * sr; v1 = fexp(e1) * sr;
            v2 = fexp(e2) * sr; v3 = fexp(e3) * sr;
        }
        s[(kq + 0) * 33 + r] = v0;
        s[(kq + 1) * 33 + r] = v1;
        s[(kq + 2) * 33 + r] = v2;
        s[(kq + 3) * 33 + r] = v3;
    }
    __syncthreads();
    #pragma unroll
    for (int i = 0; i < 8; i++) {
        int id = t + i * 256;
        int k = id >> 5, r = id & 31;
        A[(size_t)(b * K + k0 + k) * HW + hwt * 32 + r] = s[k * 33 + r];
    }
}

// ---------------- launcher: gemm->stats->awrite 3-stream chunk pipeline ----------------
extern "C" void kernel_launch(void* const* d_in, const int* in_sizes, int n_in,
                              void* d_out, int out_size) {
    const float* x0  = (const float*)d_in[0];
    const float* vq0 = (const float*)d_in[1];
    const float* vq1 = (const float*)d_in[2];
    const float* w1  = (const float*)d_in[3];
    const float* b1  = (const float*)d_in[4];
    const float* w2  = (const float*)d_in[5];
    const float* b2  = (const float*)d_in[6];
    const int*   cur = (const int*)d_in[7];

    float* out = (float*)d_out;
    float* x3  = out + OFF_X3;
    float* qx0 = out + OFF_QX0;
    float* qx3 = out + OFF_QX3;
    float* a0  = out + OFF_A0;
    float* a3  = out + OFF_A3;
    float* d0  = out + OFF_D0;
    float* d3  = out + OFF_D3;

    float *pxn0, *pxn3, *pen0, *pen1, *pdm0, *piz0, *pdm3, *piz3, *py1, *pq0;
    cudaGetSymbolAddress((void**)&pxn0, g_xn0);
    cudaGetSymbolAddress((void**)&pxn3, g_xn3);
    cudaGetSymbolAddress((void**)&pen0, g_en0);
    cudaGetSymbolAddress((void**)&pen1, g_en1);
    cudaGetSymbolAddress((void**)&pdm0, g_dm0);
    cudaGetSymbolAddress((void**)&piz0, g_iz0);
    cudaGetSymbolAddress((void**)&pdm3, g_dm3);
    cudaGetSymbolAddress((void**)&piz3, g_iz3);
    cudaGetSymbolAddress((void**)&py1,  g_y1);
    cudaGetSymbolAddress((void**)&pq0,  g_qraw0);

    static cudaStream_t sB = nullptr, sC = nullptr;
    static cudaEvent_t evF = nullptr, evP = nullptr, evJC = nullptr;
    static cudaEvent_t evG0[8] = {}, evS0[8] = {}, evG3[4] = {}, evS3[4] = {};
    if (sB == nullptr) {
        cudaStreamCreateWithFlags(&sB, cudaStreamNonBlocking);
        cudaStreamCreateWithFlags(&sC, cudaStreamNonBlocking);
        cudaEventCreateWithFlags(&evF,  cudaEventDisableTiming);
        cudaEventCreateWithFlags(&evP,  cudaEventDisableTiming);
        cudaEventCreateWithFlags(&evJC, cudaEventDisableTiming);
        for (int i = 0; i < 8; i++) {
            cudaEventCreateWithFlags(&evG0[i], cudaEventDisableTiming);
            cudaEventCreateWithFlags(&evS0[i], cudaEventDisableTiming);
        }
        for (int i = 0; i < 4; i++) {
            cudaEventCreateWithFlags(&evG3[i], cudaEventDisableTiming);
            cudaEventCreateWithFlags(&evS3[i], cudaEventDisableTiming);
        }
    }

    // fork: prep on sC (idle early), xnorm0 on main
    cudaEventRecord(evF, 0);
    cudaStreamWaitEvent(sC, evF, 0);
    prep_kernel<<<K0 + K1N, 64, 0, sC>>>(vq0, vq1, cur);
    cudaEventRecord(evP, sC);

    xnorm_kernel<C0><<<NPOS / 256, 256>>>(x0, pxn0);
    cudaStreamWaitEvent(0, evP, 0);     // gemm0 epilogue needs en0
    cudaStreamWaitEvent(sB, evP, 0);

    // level 0: gemm (main) -> stats (sB) -> awrite (sC), 8 chunks x 4 batches
    for (int c = 0; c < 8; c++) {
        gemm_kernel<64, 1, 0, 0, 2048><<<dim3(8, 100), 256>>>(x0, vq0, pxn0, pen0, d0, c * 100);
        cudaEventRecord(evG0[c], 0);
        cudaStreamWaitEvent(sB, evG0[c], 0);
        stats_kernel<2048, 64><<<6400, 256, 0, sB>>>(d0, vq0, pq0, pdm0, piz0, c * 6400);
        cudaEventRecord(evS0[c], sB);
        cudaStreamWaitEvent(sC, evS0[c], 0);
        awrite_kernel<2048><<<dim3(32, 50, 4), 256, 0, sC>>>(d0, a0, pdm0, piz0, c * 4);
    }

    // main: wait for all stats0, then qmix + head
    cudaStreamWaitEvent(0, evS0[7], 0);
    qmix_kernel<64><<<dim3(50, 2, 32), 256>>>(pq0, x0, qx0);
    gemm_kernel<64, 1, 0, 1, 256><<<dim3(1, 800), 256>>>(qx0, w1, nullptr, b1, py1, 0);
    gemm_kernel<256, 0, 1, 2, 256><<<dim3(1, 800), 256>>>(py1, w2, nullptr, b2, x3, 0);
    xnorm_kernel<C1><<<NPOS / 256, 256>>>(x3, pxn3);

    // level 3: gemm (main) -> stats (sB) -> awrite (sC), 4 chunks x 8 batches
    for (int c = 0; c < 4; c++) {
        gemm_kernel<256, 1, 0, 0, 512><<<dim3(2, 200), 256>>>(x3, vq1, pxn3, pen1, d3, c * 200);
        cudaEventRecord(evG3[c], 0);
        cudaStreamWaitEvent(sB, evG3[c], 0);
        stats_kernel<512, 256><<<12800, 256, 0, sB>>>(d3, vq1, py1, pdm3, piz3, c * 12800);
        cudaEventRecord(evS3[c], sB);
        cudaStreamWaitEvent(sC, evS3[c], 0);
        awrite_kernel<512><<<dim3(8, 50, 8), 256, 0, sC>>>(d3, a3, pdm3, piz3, c * 8);
    }

    // main: wait all stats3, produce qx3
    cudaStreamWaitEvent(0, evS3[3], 0);
    qmix_kernel<256><<<dim3(50, 8, 32), 256>>>(py1, x3, qx3);

    // join: sC (all awrites, in-order) into main
    cudaEventRecord(evJC, sC);
    cudaStreamWaitEvent(0, evJC, 0);
}